// round 8
// baseline (speedup 1.0000x reference)
#include <cuda_runtime.h>
#include <cuda_bf16.h>
#include <cstdint>

// ---------------- problem constants ----------------
#define NNODES 50000
#define NEDGES 800000
#define NCTA   148
#define NTHR   512
#define NGTH   (NCTA * NTHR)            // 75776 threads
#define NWARPS (NCTA * (NTHR / 32))     // 2368 warps
#define CH     338                      // nodes per CTA chunk (148*338 = 50024)
#define GT     ((NNODES + 127) / 128)   // 391 GEMM tiles

// ---------------- device scratch (no allocs allowed) ----------------
__device__ int      g_src[NEDGES];
__device__ int      g_dst[NEDGES];
__device__ int      g_deg[NNODES];
__device__ int      g_rowptr[NNODES + 1];
__device__ int      g_fill[NNODES];
__device__ int      g_csrc[NEDGES];
__device__ int      g_bsum[NCTA];
__device__ float    g_dinv[NNODES];
__device__ uint2    g_zb[NNODES * 32];   // z bf16: 128 cols = 32 uint2
__device__ float    g_y[NNODES * 128];
__device__ float    g_h[NNODES * 128];
__device__ unsigned g_barcnt;            // software grid barrier
__device__ unsigned g_bargen;

__device__ __forceinline__ float to_tf32(float x) {
    float r;
    asm("cvt.rna.tf32.f32 %0, %1;" : "=f"(r) : "f"(x));
    return r;
}

// sense-reversing grid barrier; safe because all 148 CTAs are co-resident
// (1 CTA/SM forced by the 198KB smem request, 148 <= SM count).
__device__ __forceinline__ void gsync() {
    __syncthreads();
    if (threadIdx.x == 0) {
        __threadfence();
        unsigned gen = *(volatile unsigned*)&g_bargen;
        if (atomicAdd(&g_barcnt, 1u) == NCTA - 1) {
            g_barcnt = 0;
            __threadfence();
            *(volatile unsigned*)&g_bargen = gen + 1;
        } else {
            while (*(volatile unsigned*)&g_bargen == gen) { }
        }
        __threadfence();
    }
    __syncthreads();
}

// ---------------- GEMM phase (mma.sync tf32 dual output) ----------------
template <int NC>
__device__ void gemm_phase(float* smem, const float* __restrict__ H,
                           const float* __restrict__ Wl, const float* __restrict__ Wr,
                           __nv_bfloat162* __restrict__ Zb, float* __restrict__ Y) {
    constexpr int D  = NC / 2;
    constexpr int NT = NC / 32;
    constexpr int ST = 132;
    float* sA = smem;                 // 128 x ST
    float* sB = smem + 128 * ST;      // NC x ST

    const int tid  = threadIdx.x;
    const int wid  = tid >> 5;
    const int lane = tid & 31;
    const int warp_m = wid & 3;
    const int warp_n = wid >> 2;
    const int lm = lane >> 2;
    const int lk = lane & 3;

    for (int tile = blockIdx.x; tile < GT; tile += NCTA) {
        const int row0 = tile * 128;
        __syncthreads();              // previous tile's smem reads complete
        {
            const float4* h4 = (const float4*)H;
            #pragma unroll
            for (int i = tid; i < 128 * 32; i += NTHR) {
                int r = i >> 5, c = i & 31;
                int gr = row0 + r;
                float4 v = make_float4(0.f, 0.f, 0.f, 0.f);
                if (gr < NNODES) v = h4[gr * 32 + c];
                float* p = &sA[r * ST + c * 4];
                p[0] = to_tf32(v.x); p[1] = to_tf32(v.y);
                p[2] = to_tf32(v.z); p[3] = to_tf32(v.w);
            }
        }
        {
            #pragma unroll
            for (int i = tid; i < NC * 32; i += NTHR) {
                int n = i >> 5, c = i & 31;
                const float4* wsrc = (const float4*)((n < D) ? (Wl + n * 128)
                                                             : (Wr + (n - D) * 128));
                float4 v = wsrc[c];
                float* p = &sB[n * ST + c * 4];
                p[0] = to_tf32(v.x); p[1] = to_tf32(v.y);
                p[2] = to_tf32(v.z); p[3] = to_tf32(v.w);
            }
        }
        __syncthreads();

        float acc[2][NT][4];
        #pragma unroll
        for (int mi = 0; mi < 2; ++mi)
            #pragma unroll
            for (int ni = 0; ni < NT; ++ni)
                #pragma unroll
                for (int q = 0; q < 4; ++q) acc[mi][ni][q] = 0.f;

        #pragma unroll
        for (int kk = 0; kk < 16; ++kk) {
            const int k0 = kk * 8;
            uint32_t a[2][4];
            #pragma unroll
            for (int mi = 0; mi < 2; ++mi) {
                const int rb = warp_m * 32 + mi * 16;
                a[mi][0] = *(const uint32_t*)&sA[(rb + lm)     * ST + k0 + lk];
                a[mi][1] = *(const uint32_t*)&sA[(rb + 8 + lm) * ST + k0 + lk];
                a[mi][2] = *(const uint32_t*)&sA[(rb + lm)     * ST + k0 + 4 + lk];
                a[mi][3] = *(const uint32_t*)&sA[(rb + 8 + lm) * ST + k0 + 4 + lk];
            }
            uint32_t b[NT][2];
            #pragma unroll
            for (int ni = 0; ni < NT; ++ni) {
                const int nb = warp_n * (NT * 8) + ni * 8;
                b[ni][0] = *(const uint32_t*)&sB[(nb + lm) * ST + k0 + lk];
                b[ni][1] = *(const uint32_t*)&sB[(nb + lm) * ST + k0 + 4 + lk];
            }
            #pragma unroll
            for (int mi = 0; mi < 2; ++mi)
                #pragma unroll
                for (int ni = 0; ni < NT; ++ni) {
                    asm volatile(
                        "mma.sync.aligned.m16n8k8.row.col.f32.tf32.tf32.f32 "
                        "{%0,%1,%2,%3}, {%4,%5,%6,%7}, {%8,%9}, {%0,%1,%2,%3};"
                        : "+f"(acc[mi][ni][0]), "+f"(acc[mi][ni][1]),
                          "+f"(acc[mi][ni][2]), "+f"(acc[mi][ni][3])
                        : "r"(a[mi][0]), "r"(a[mi][1]), "r"(a[mi][2]), "r"(a[mi][3]),
                          "r"(b[ni][0]), "r"(b[ni][1]));
                }
        }

        const bool yhalf = (warp_n >= 2);
        const int cbase = warp_n * (NT * 8) - (yhalf ? D : 0);
        #pragma unroll
        for (int mi = 0; mi < 2; ++mi) {
            const int rl = row0 + warp_m * 32 + mi * 16 + lm;
            const int rh = rl + 8;
            #pragma unroll
            for (int ni = 0; ni < NT; ++ni) {
                const int oc = cbase + ni * 8 + lk * 2;
                if (yhalf) {
                    if (rl < NNODES)
                        *(float2*)&Y[rl * D + oc] = make_float2(acc[mi][ni][0], acc[mi][ni][1]);
                    if (rh < NNODES)
                        *(float2*)&Y[rh * D + oc] = make_float2(acc[mi][ni][2], acc[mi][ni][3]);
                } else {
                    if (rl < NNODES)
                        Zb[rl * (D / 2) + oc / 2] =
                            __float22bfloat162_rn(make_float2(acc[mi][ni][0], acc[mi][ni][1]));
                    if (rh < NNODES)
                        Zb[rh * (D / 2) + oc / 2] =
                            __float22bfloat162_rn(make_float2(acc[mi][ni][2], acc[mi][ni][3]));
                }
            }
        }
    }
}

// ---------------- gather phases ----------------
__device__ void gather128_phase(const uint2* __restrict__ Zb, const float* __restrict__ Yb,
                                const float* __restrict__ bias, float* __restrict__ Hout) {
    const int lane = threadIdx.x & 31;
    const int w0 = blockIdx.x * (NTHR / 32) + (threadIdx.x >> 5);
    for (int w = w0; w < NNODES; w += NWARPS) {
        int j = g_rowptr[w];
        int e = g_rowptr[w + 1];
        float4 a0 = make_float4(0.f, 0.f, 0.f, 0.f);
        float4 a1 = make_float4(0.f, 0.f, 0.f, 0.f);
        for (; j + 1 < e; j += 2) {
            int s0 = g_csrc[j], s1 = g_csrc[j + 1];
            uint2 u0 = Zb[s0 * 32 + lane];
            uint2 u1 = Zb[s1 * 32 + lane];
            float2 f00 = __bfloat1622float2(*(const __nv_bfloat162*)&u0.x);
            float2 f01 = __bfloat1622float2(*(const __nv_bfloat162*)&u0.y);
            float2 f10 = __bfloat1622float2(*(const __nv_bfloat162*)&u1.x);
            float2 f11 = __bfloat1622float2(*(const __nv_bfloat162*)&u1.y);
            a0.x += f00.x; a0.y += f00.y; a0.z += f01.x; a0.w += f01.y;
            a1.x += f10.x; a1.y += f10.y; a1.z += f11.x; a1.w += f11.y;
        }
        if (j < e) {
            int s0 = g_csrc[j];
            uint2 u0 = Zb[s0 * 32 + lane];
            float2 f00 = __bfloat1622float2(*(const __nv_bfloat162*)&u0.x);
            float2 f01 = __bfloat1622float2(*(const __nv_bfloat162*)&u0.y);
            a0.x += f00.x; a0.y += f00.y; a0.z += f01.x; a0.w += f01.y;
        }
        float inv = g_dinv[w];
        float4 yv = ((const float4*)Yb)[w * 32 + lane];
        float4 bv = ((const float4*)bias)[lane];
        float4 o;
        o.x = fmaxf((a0.x + a1.x) * inv + yv.x + bv.x, 0.f);
        o.y = fmaxf((a0.y + a1.y) * inv + yv.y + bv.y, 0.f);
        o.z = fmaxf((a0.z + a1.z) * inv + yv.z + bv.z, 0.f);
        o.w = fmaxf((a0.w + a1.w) * inv + yv.w + bv.w, 0.f);
        ((float4*)Hout)[w * 32 + lane] = o;
    }
}

__device__ void gather_final_phase(const unsigned* __restrict__ Zb,
                                   const float* __restrict__ Yb,
                                   const float* __restrict__ bias,
                                   float* __restrict__ out) {
    const int lane = threadIdx.x & 31;
    const int w0 = blockIdx.x * (NTHR / 32) + (threadIdx.x >> 5);
    for (int w = w0; w < NNODES; w += NWARPS) {
        int j = g_rowptr[w];
        int e = g_rowptr[w + 1];
        float2 a0 = make_float2(0.f, 0.f);
        float2 a1 = make_float2(0.f, 0.f);
        for (; j + 1 < e; j += 2) {
            int s0 = g_csrc[j], s1 = g_csrc[j + 1];
            unsigned u0 = Zb[s0 * 32 + lane];
            unsigned u1 = Zb[s1 * 32 + lane];
            float2 f0 = __bfloat1622float2(*(const __nv_bfloat162*)&u0);
            float2 f1 = __bfloat1622float2(*(const __nv_bfloat162*)&u1);
            a0.x += f0.x; a0.y += f0.y;
            a1.x += f1.x; a1.y += f1.y;
        }
        if (j < e) {
            int s0 = g_csrc[j];
            unsigned u0 = Zb[s0 * 32 + lane];
            float2 f0 = __bfloat1622float2(*(const __nv_bfloat162*)&u0);
            a0.x += f0.x; a0.y += f0.y;
        }
        float inv = g_dinv[w];
        float2 yv = ((const float2*)Yb)[w * 32 + lane];
        float2 bv = ((const float2*)bias)[lane];
        float v0 = (a0.x + a1.x) * inv + yv.x + bv.x;
        float v1 = (a0.y + a1.y) * inv + yv.y + bv.y;
        float m = fmaxf(v0, v1);
        #pragma unroll
        for (int o = 16; o; o >>= 1) m = fmaxf(m, __shfl_xor_sync(0xffffffffu, m, o));
        float s = expf(v0 - m) + expf(v1 - m);
        #pragma unroll
        for (int o = 16; o; o >>= 1) s += __shfl_xor_sync(0xffffffffu, s, o);
        float lse = m + logf(s);
        out[w * 64 + lane * 2 + 0] = v0 - lse;
        out[w * 64 + lane * 2 + 1] = v1 - lse;
    }
}

// ---------------- the fused persistent kernel ----------------
__global__ __launch_bounds__(NTHR, 1)
void k_fused(const float* __restrict__ x, const void* __restrict__ ei,
             const float* __restrict__ Wl0, const float* __restrict__ bl0,
             const float* __restrict__ Wr0,
             const float* __restrict__ Wl1, const float* __restrict__ bl1,
             const float* __restrict__ Wr1,
             const float* __restrict__ Wl2, const float* __restrict__ bl2,
             const float* __restrict__ Wr2,
             float* __restrict__ out) {
    extern __shared__ float smem[];
    const int tid  = threadIdx.x;
    const int cta  = blockIdx.x;
    const int gtid = cta * NTHR + tid;

    // ---- P0: zero deg/fill ----
    for (int i = gtid; i < NNODES; i += NGTH) { g_deg[i] = 0; g_fill[i] = 0; }

    // ---- P0b: layer-0 GEMM (edge-independent; fills the slack pre-barrier) ----
    gemm_phase<256>(smem, x, Wl0, Wr0, (__nv_bfloat162*)g_zb, g_y);
    gsync();

    // ---- P1: edge decode + degree ----
    {
        const long long* e64 = (const long long*)ei;
        bool is32 = false;
        #pragma unroll
        for (int q = 0; q < 4; ++q) {
            long long v = e64[q];
            if (v < 0 || v >= NNODES) is32 = true;
        }
        if (is32) {
            const int* e = (const int*)ei;
            for (int i = gtid; i < NEDGES; i += NGTH) {
                int d = e[i], s = e[NEDGES + i];
                g_dst[i] = d; g_src[i] = s;
                atomicAdd(&g_deg[d], 1);
            }
        } else {
            for (int i = gtid; i < NEDGES; i += NGTH) {
                int d = (int)e64[i], s = (int)e64[NEDGES + i];
                g_dst[i] = d; g_src[i] = s;
                atomicAdd(&g_deg[d], 1);
            }
        }
    }
    gsync();

    // ---- P2: local inclusive scan of this CTA's chunk (smem persists) ----
    int* sscan = (int*)smem;            // 512 ints
    int* sred  = (int*)smem + NTHR;     // 512 ints
    const int base = cta * CH;
    {
        int v = 0;
        if (tid < CH && base + tid < NNODES) v = g_deg[base + tid];
        sscan[tid] = v;
        __syncthreads();
        #pragma unroll
        for (int off = 1; off < NTHR; off <<= 1) {
            int t = (tid >= off) ? sscan[tid - off] : 0;
            __syncthreads();
            sscan[tid] += t;
            __syncthreads();
        }
        if (tid == NTHR - 1) g_bsum[cta] = sscan[tid];
    }
    gsync();

    // ---- P3: global offsets + write rowptr/dinv ----
    {
        int p = (tid < cta) ? g_bsum[tid] : 0;   // cta < 148 < 512
        sred[tid] = p;
        __syncthreads();
        #pragma unroll
        for (int off = NTHR / 2; off > 0; off >>= 1) {
            if (tid < off) sred[tid] += sred[tid + off];
            __syncthreads();
        }
        int offset = sred[0];
        if (cta == 0 && tid == 0) g_rowptr[0] = 0;
        if (tid < CH && base + tid < NNODES) {
            g_rowptr[base + tid + 1] = sscan[tid] + offset;
            g_dinv[base + tid] = 1.0f / fmaxf((float)g_deg[base + tid], 1.0f);
        }
    }
    gsync();

    // ---- P4: CSR fill ----
    for (int i = gtid; i < NEDGES; i += NGTH) {
        int d = g_dst[i];
        int pos = g_rowptr[d] + atomicAdd(&g_fill[d], 1);
        g_csrc[pos] = g_src[i];
    }
    gsync();

    // ---- P5: layer-0 gather/combine -> h ----
    gather128_phase((const uint2*)g_zb, g_y, bl0, g_h);
    gsync();

    // ---- P6: layer-1 GEMM ----
    gemm_phase<256>(smem, g_h, Wl1, Wr1, (__nv_bfloat162*)g_zb, g_y);
    gsync();

    // ---- P7: layer-1 gather/combine -> h ----
    gather128_phase((const uint2*)g_zb, g_y, bl1, g_h);
    gsync();

    // ---- P8: layer-2 GEMM (NC=128) ----
    gemm_phase<128>(smem, g_h, Wl2, Wr2, (__nv_bfloat162*)g_zb, g_y);
    gsync();

    // ---- P9: final gather + log_softmax -> out ----
    gather_final_phase((const unsigned*)g_zb, g_y, bl2, out);
}

// ---------------- host launch ----------------
extern "C" void kernel_launch(void* const* d_in, const int* in_sizes, int n_in,
                              void* d_out, int out_size) {
    const float* x   = (const float*)d_in[0];
    const void*  ei  = d_in[1];
    const float* Wl0 = (const float*)d_in[2];
    const float* bl0 = (const float*)d_in[3];
    const float* Wr0 = (const float*)d_in[4];
    const float* Wl1 = (const float*)d_in[5];
    const float* bl1 = (const float*)d_in[6];
    const float* Wr1 = (const float*)d_in[7];
    const float* Wl2 = (const float*)d_in[8];
    const float* bl2 = (const float*)d_in[9];
    const float* Wr2 = (const float*)d_in[10];
    float* out = (float*)d_out;
    (void)in_sizes; (void)n_in; (void)out_size;

    const int SMEM = (128 * 132 + 256 * 132) * 4;   // 202752
    cudaFuncSetAttribute(k_fused, cudaFuncAttributeMaxDynamicSharedMemorySize, SMEM);

    k_fused<<<NCTA, NTHR, SMEM>>>(x, ei, Wl0, bl0, Wr0, Wl1, bl1, Wr1, Wl2, bl2, Wr2, out);
}